// round 14
// baseline (speedup 1.0000x reference)
#include <cuda_runtime.h>
#include <cuda_fp16.h>
#include <math.h>
#include <stdint.h>

#define NN   200000
#define EE   300000
#define ETOT (3 * EE)
#define BB   64
#define HID  128
#define NHEAD 4
#define NREL 3
#define TED  64
#define TASK 384
#define INV_SQRT_D 0.17677669529663687f

// ---------------- scratch ----------------------------------------------------
__device__ float  g_h[NN * HID];           // fp32 node features
__device__ __half g_hh[NN * HID];          // fp16 shadow of g_h (GEMM A operand)
__device__ __half g_qh[NN * HID];          // queries fp16
__device__ __half g_kt[NREL][NN * HID];    // per-relation transformed keys
__device__ __half g_vt[NREL][NN * HID];    // per-relation transformed values
__device__ __half g_W1[128 * 896];         // fused weight [k=128][n=896]
__device__ float  g_b1[896];               // fused bias
__device__ __half g_W2[128 * 128];         // Wout fp16 [k][n]
__device__ __half g_aggh[NN * HID];        // gelu(agg) fp16
__device__ int    g_deg[NN];
__device__ int    g_off[NN + 1];
__device__ int    g_cur[NN];
__device__ int    g_edge[ETOT];            // src | (rel<<18), CSR order
__device__ float  g_pool[2 * BB * HID];
__device__ float  g_cnt[2 * BB];
__device__ float  g_ge[BB * 256];

// ---------------- helpers ----------------------------------------------------
__device__ __forceinline__ float gelu_f(float v) {
    return 0.5f * v * (1.0f + erff(v * 0.70710678118654752f));
}
#define PACKW(d_, lo_, hi_) asm("mov.b64 %0, {%1, %2};" : "=l"(d_) : "f"(lo_), "f"(hi_))
#define UNPK2(lo, hi, s) asm("mov.b64 {%0, %1}, %2;" : "=f"(lo), "=f"(hi) : "l"(s))
#define FFMA2(c_, a_, b_) \
    asm("fma.rn.f32x2 %0, %1, %2, %3;" : "=l"(c_) : "l"(a_), "l"(b_), "l"(c_))

__device__ __forceinline__ unsigned int smem_u32(const void* p) {
    return (unsigned int)__cvta_generic_to_shared(p);
}
#define CP_ASYNC16(dst, src) \
    asm volatile("cp.async.cg.shared.global [%0], [%1], 16;" :: "r"(dst), "l"(src))
#define CP_COMMIT() asm volatile("cp.async.commit_group;")
#define CP_WAIT(n)  asm volatile("cp.async.wait_group %0;" :: "n"(n))

#define LDSM_X4(r0,r1,r2,r3,addr) \
    asm volatile("ldmatrix.sync.aligned.m8n8.x4.shared.b16 {%0,%1,%2,%3}, [%4];" \
        : "=r"(r0),"=r"(r1),"=r"(r2),"=r"(r3) : "r"(addr))
#define LDSM_X4T(r0,r1,r2,r3,addr) \
    asm volatile("ldmatrix.sync.aligned.m8n8.x4.trans.shared.b16 {%0,%1,%2,%3}, [%4];" \
        : "=r"(r0),"=r"(r1),"=r"(r2),"=r"(r3) : "r"(addr))
#define MMA16816(d, a, b) \
    asm volatile("mma.sync.aligned.m16n8k16.row.col.f32.f16.f16.f32 " \
        "{%0,%1,%2,%3}, {%4,%5,%6,%7}, {%8,%9}, {%0,%1,%2,%3};" \
        : "+f"((d)[0]), "+f"((d)[1]), "+f"((d)[2]), "+f"((d)[3]) \
        : "r"((a)[0]), "r"((a)[1]), "r"((a)[2]), "r"((a)[3]), \
          "r"((b)[0]), "r"((b)[1]))

__global__ void k_fill(float* p, float v, int n) {
    int i = blockIdx.x * blockDim.x + threadIdx.x;
    if (i < n) p[i] = v;
}
__global__ void k_filli(int* p, int v, int n) {
    int i = blockIdx.x * blockDim.x + threadIdx.x;
    if (i < n) p[i] = v;
}

// ---------------- CSR build ---------------------------------------------------
__global__ void k_hist(const int* __restrict__ e0, const int* __restrict__ e1,
                       const int* __restrict__ e2) {
    int g = blockIdx.x * blockDim.x + threadIdx.x;
    if (g >= ETOT) return;
    int r = g / EE, e = g - r * EE;
    const int* ei = (r == 0) ? e0 : ((r == 1) ? e1 : e2);
    atomicAdd(&g_deg[ei[EE + e]], 1);
}

__global__ void k_scan() {   // single block, 1024 threads
    __shared__ int part[1024];
    int tid = threadIdx.x;
    const int CH = (NN + 1023) / 1024;
    int b0 = tid * CH, b1 = min(b0 + CH, NN);
    int s = 0;
    for (int i = b0; i < b1; i++) s += g_deg[i];
    part[tid] = s;
    __syncthreads();
    for (int off = 1; off < 1024; off <<= 1) {
        int v = (tid >= off) ? part[tid - off] : 0;
        __syncthreads();
        part[tid] += v;
        __syncthreads();
    }
    int run = (tid > 0) ? part[tid - 1] : 0;
    for (int i = b0; i < b1; i++) {
        int d = g_deg[i];
        g_off[i] = run;
        g_cur[i] = run;
        run += d;
    }
    if (tid == 1023) g_off[NN] = run;
}

__global__ void k_scatter(const int* __restrict__ e0, const int* __restrict__ e1,
                          const int* __restrict__ e2) {
    int g = blockIdx.x * blockDim.x + threadIdx.x;
    if (g >= ETOT) return;
    int r = g / EE, e = g - r * EE;
    const int* ei = (r == 0) ? e0 : ((r == 1) ? e1 : e2);
    int src = ei[e], dst = ei[EE + e];
    int pos = atomicAdd(&g_cur[dst], 1);
    g_edge[pos] = src | (r << 18);
}

// ---------------- input embed (FFMA2), writes fp32 + fp16 --------------------
__global__ void k_embed(const float* __restrict__ x, const int* __restrict__ ast,
                        const float* __restrict__ emb, const float* __restrict__ Win,
                        const float* __restrict__ bin) {
    __shared__ float sA[32][70];
    int tid = threadIdx.x;            // 128 = one output column per thread
    int c = tid;
    unsigned long long w2[34];
    #pragma unroll
    for (int t = 0; t < 34; t++) {
        float w0 = Win[(2 * t) * 128 + c];
        float w1 = Win[(2 * t + 1) * 128 + c];
        PACKW(w2[t], w0, w1);
    }
    float wl = Win[68 * 128 + c];
    float bv = bin[c];
    int n0 = blockIdx.x * 32;
    for (int idx = tid; idx < 32 * 69; idx += 128) {
        int i = idx / 69, k = idx - i * 69;
        int n = n0 + i;
        sA[i][k] = (k < TED) ? emb[ast[n] * TED + k] : x[n * 5 + (k - TED)];
    }
    __syncthreads();
    for (int i = 0; i < 32; i++) {
        const unsigned long long* ap = (const unsigned long long*)&sA[i][0];
        unsigned long long acc2 = 0ULL;
        #pragma unroll
        for (int t = 0; t < 34; t++) FFMA2(acc2, ap[t], w2[t]);
        float lo, hi;
        UNPK2(lo, hi, acc2);
        float val = bv + sA[i][68] * wl + lo + hi;
        g_h[(n0 + i) * HID + c] = val;
        g_hh[(n0 + i) * HID + c] = __float2half(val);
    }
}

// ---------------- combine weights: W1 = [Wq | Wk@Wk_rel | Wv@Wv_rel] ---------
__global__ void k_combine(const float* __restrict__ Wkqv, const float* __restrict__ bkqv,
                          const float* __restrict__ Wk_rel, const float* __restrict__ Wv_rel,
                          int l) {
    int n = blockIdx.x;      // 0..895
    int k = threadIdx.x;     // 0..127
    const float* Wl = Wkqv + l * 128 * 384;
    const float* bl = bkqv + l * 384;
    if (n < 128) {
        g_W1[k * 896 + n] = __float2half(Wl[k * 384 + 128 + n]);
        if (k == 0) g_b1[n] = bl[128 + n];
        return;
    }
    int g = n - 128;
    int kv = g / 384;
    int rem = g - kv * 384;
    int r = rem >> 7;
    int c = rem & 127;
    int h = c >> 5, f = c & 31;
    const float* Wrel = ((kv == 0) ? Wk_rel : Wv_rel) + ((l * NREL + r) * NHEAD + h) * 1024;
    __shared__ float wcol[32];
    if (k < 32) wcol[k] = Wrel[k * 32 + f];
    __syncthreads();
    int off = (kv == 0) ? 0 : 256;
    const float* wrow = Wl + k * 384 + off + h * 32;
    float acc = 0.f;
    #pragma unroll
    for (int d = 0; d < 32; d++) acc += wrow[d] * wcol[d];
    g_W1[k * 896 + n] = __float2half(acc);
    if (k == 0) {
        float b = 0.f;
        #pragma unroll
        for (int d = 0; d < 32; d++) b += bl[off + h * 32 + d] * wcol[d];
        g_b1[n] = b;
    }
}

// ---------------- Wout -> fp16 ------------------------------------------------
__global__ void k_wcvt(const float* __restrict__ Wout, int l) {
    int i = blockIdx.x * blockDim.x + threadIdx.x;
    if (i < 128 * 128) g_W2[i] = __float2half(Wout[l * 128 * 128 + i]);
}

// ---------------- fused q/kt/vt GEMM: A loaded ONCE, 7 column tiles ----------
// dyn smem: sA[128][136] + sB[2][128][136]  (~102 KB)
__global__ __launch_bounds__(256)
void k_gemm_big() {
    extern __shared__ __half dsm[];
    __half (*sA)[136] = (__half(*)[136])dsm;                 // 128 x 136
    __half (*sB0)[136] = (__half(*)[136])(dsm + 128 * 136);  // stage 0
    __half (*sB1)[136] = (__half(*)[136])(dsm + 2 * 128 * 136);

    int tid = threadIdx.x;
    int wid = tid >> 5, lane = tid & 31;
    int warp_m = (wid >> 2) * 64;
    int warp_n = (wid & 3) * 32;
    int row0 = blockIdx.x * 128;

    int arow = tid >> 1, acol = (tid & 1) * 64;
    int gr = row0 + arow; if (gr >= NN) gr = NN - 1;
    const __half* agp = &g_hh[gr * 128 + acol];

    // load A (whole 128x128) + B tile 0 in group 0
    {
        unsigned int dA = smem_u32(&sA[arow][acol]);
        #pragma unroll
        for (int j = 0; j < 8; j++) CP_ASYNC16(dA + j * 16, agp + j * 8);
        unsigned int dB = smem_u32(&sB0[arow][acol]);
        const __half* srcB = &g_W1[arow * 896 + acol];
        #pragma unroll
        for (int j = 0; j < 8; j++) CP_ASYNC16(dB + j * 16, srcB + j * 8);
        CP_COMMIT();
    }
    // B tile 1 in group 1
    {
        unsigned int dB = smem_u32(&sB1[arow][acol]);
        const __half* srcB = &g_W1[arow * 896 + 128 + acol];
        #pragma unroll
        for (int j = 0; j < 8; j++) CP_ASYNC16(dB + j * 16, srcB + j * 8);
        CP_COMMIT();
    }

    int qrow = lane >> 2;
    int qcol = (lane & 3) * 2;

    #pragma unroll
    for (int y = 0; y < 7; y++) {
        __half (*sB)[136] = (y & 1) ? sB1 : sB0;
        if (y == 6) { CP_WAIT(0); } else { CP_WAIT(1); }
        __syncthreads();

        float acc[4][4][4];
        #pragma unroll
        for (int mi = 0; mi < 4; mi++)
            #pragma unroll
            for (int ni = 0; ni < 4; ni++)
                #pragma unroll
                for (int j = 0; j < 4; j++) acc[mi][ni][j] = 0.0f;

        #pragma unroll
        for (int k16 = 0; k16 < 128; k16 += 16) {
            unsigned int af[4][4];
            #pragma unroll
            for (int mi = 0; mi < 4; mi++) {
                unsigned int ad = smem_u32(&sA[warp_m + mi * 16 + (lane & 15)][k16 + (lane >> 4) * 8]);
                LDSM_X4(af[mi][0], af[mi][1], af[mi][2], af[mi][3], ad);
            }
            unsigned int bf[4][2];
            #pragma unroll
            for (int nb = 0; nb < 2; nb++) {
                unsigned int bd = smem_u32(&sB[k16 + (lane & 15)][warp_n + nb * 16 + (lane >> 4) * 8]);
                unsigned int b0, b1_, b2, b3;
                LDSM_X4T(b0, b1_, b2, b3, bd);
                bf[nb * 2][0] = b0;     bf[nb * 2][1] = b1_;
                bf[nb * 2 + 1][0] = b2; bf[nb * 2 + 1][1] = b3;
            }
            #pragma unroll
            for (int mi = 0; mi < 4; mi++)
                #pragma unroll
                for (int ni = 0; ni < 4; ni++)
                    MMA16816(acc[mi][ni], af[mi], bf[ni]);
        }
        __syncthreads();   // all warps done reading sB[y&1] before prefetch overwrite

        if (y + 2 < 7) {
            __half (*sBn)[136] = (y & 1) ? sB1 : sB0;
            unsigned int dB = smem_u32(&sBn[arow][acol]);
            const __half* srcB = &g_W1[arow * 896 + (y + 2) * 128 + acol];
            #pragma unroll
            for (int j = 0; j < 8; j++) CP_ASYNC16(dB + j * 16, srcB + j * 8);
            CP_COMMIT();
        }

        // epilogue for tile y (registers only; overlaps with prefetch)
        int ncol0 = y * 128;
        __half* dsth = (y == 0) ? g_qh : ((y <= 3) ? g_kt[y - 1] : g_vt[y - 4]);
        #pragma unroll
        for (int ni = 0; ni < 4; ni++) {
            int col = warp_n + ni * 8 + qcol;
            float b0v = g_b1[ncol0 + col];
            float b1v = g_b1[ncol0 + col + 1];
            #pragma unroll
            for (int mi = 0; mi < 4; mi++) {
                int r1 = row0 + warp_m + mi * 16 + qrow;
                int r2 = r1 + 8;
                float v00 = acc[mi][ni][0] + b0v, v01 = acc[mi][ni][1] + b1v;
                float v10 = acc[mi][ni][2] + b0v, v11 = acc[mi][ni][3] + b1v;
                if (r1 < NN) *(__half2*)&dsth[r1 * 128 + col] = __floats2half2_rn(v00, v01);
                if (r2 < NN) *(__half2*)&dsth[r2 * 128 + col] = __floats2half2_rn(v10, v11);
            }
        }
    }
}

// ---------------- fused edge attention: 2-state online softmax ---------------
__global__ __launch_bounds__(256)
void k_edge(const float* __restrict__ prel) {
    int gw = (blockIdx.x * blockDim.x + threadIdx.x) >> 5;
    if (gw >= NN) return;
    int lane = threadIdx.x & 31;
    int h = lane >> 3;
    float p0 = prel[h] * INV_SQRT_D;
    float p1 = prel[4 + h] * INV_SQRT_D;
    float p2 = prel[8 + h] * INV_SQRT_D;
    uint2 qraw = *(const uint2*)&g_qh[gw * 128 + lane * 4];
    float2 q0 = __half22float2(*(__half2*)&qraw.x);
    float2 q1 = __half22float2(*(__half2*)&qraw.y);
    int e0 = g_off[gw], e1 = g_off[gw + 1];
    float mA = -INFINITY, zA = 0.0f;
    float mB = -INFINITY, zB = 0.0f;
    float4 aA = make_float4(0.f, 0.f, 0.f, 0.f);
    float4 aB = make_float4(0.f, 0.f, 0.f, 0.f);
    if (e0 < e1) {
        int pkA = g_edge[e0], pkB = 0;
        uint2 kA, vA;
        uint2 kB = make_uint2(0u, 0u), vB = make_uint2(0u, 0u);
        {
            int s = pkA & 0x3FFFF, r = pkA >> 18;
            kA = *(const uint2*)&g_kt[r][s * 128 + lane * 4];
            vA = *(const uint2*)&g_vt[r][s * 128 + lane * 4];
        }
        if (e0 + 1 < e1) {
            pkB = g_edge[e0 + 1];
            int s = pkB & 0x3FFFF, r = pkB >> 18;
            kB = *(const uint2*)&g_kt[r][s * 128 + lane * 4];
            vB = *(const uint2*)&g_vt[r][s * 128 + lane * 4];
        }
        for (int i = e0; i < e1; i += 2) {
            int rcA = pkA >> 18; uint2 kcA = kA, vcA = vA;
            bool hasB = (i + 1 < e1);
            int rcB = pkB >> 18; uint2 kcB = kB, vcB = vB;
            if (i + 2 < e1) {
                pkA = g_edge[i + 2];
                int s = pkA & 0x3FFFF, r = pkA >> 18;
                kA = *(const uint2*)&g_kt[r][s * 128 + lane * 4];
                vA = *(const uint2*)&g_vt[r][s * 128 + lane * 4];
            }
            if (i + 3 < e1) {
                pkB = g_edge[i + 3];
                int s = pkB & 0x3FFFF, r = pkB >> 18;
                kB = *(const uint2*)&g_kt[r][s * 128 + lane * 4];
                vB = *(const uint2*)&g_vt[r][s * 128 + lane * 4];
            }
            float2 ka0 = __half22float2(*(__half2*)&kcA.x);
            float2 ka1 = __half22float2(*(__half2*)&kcA.y);
            float sA_ = q0.x * ka0.x + q0.y * ka0.y + q1.x * ka1.x + q1.y * ka1.y;
            float2 kb0 = __half22float2(*(__half2*)&kcB.x);
            float2 kb1 = __half22float2(*(__half2*)&kcB.y);
            float sB_ = q0.x * kb0.x + q0.y * kb0.y + q1.x * kb1.x + q1.y * kb1.y;
            sA_ += __shfl_xor_sync(0xffffffffu, sA_, 1);
            sB_ += __shfl_xor_sync(0xffffffffu, sB_, 1);
            sA_ += __shfl_xor_sync(0xffffffffu, sA_, 2);
            sB_ += __shfl_xor_sync(0xffffffffu, sB_, 2);
            sA_ += __shfl_xor_sync(0xffffffffu, sA_, 4);
            sB_ += __shfl_xor_sync(0xffffffffu, sB_, 4);
            sA_ *= (rcA == 0) ? p0 : ((rcA == 1) ? p1 : p2);
            sB_ *= (rcB == 0) ? p0 : ((rcB == 1) ? p1 : p2);
            {
                float mn = fmaxf(mA, sA_);
                float es = __expf(sA_ - mn);
                float co = __expf(mA - mn);
                mA = mn;
                float2 v0 = __half22float2(*(__half2*)&vcA.x);
                float2 v1 = __half22float2(*(__half2*)&vcA.y);
                zA = zA * co + es;
                aA.x = aA.x * co + es * v0.x;
                aA.y = aA.y * co + es * v0.y;
                aA.z = aA.z * co + es * v1.x;
                aA.w = aA.w * co + es * v1.y;
            }
            if (hasB) {
                float mn = fmaxf(mB, sB_);
                float es = __expf(sB_ - mn);
                float co = __expf(mB - mn);
                mB = mn;
                float2 v0 = __half22float2(*(__half2*)&vcB.x);
                float2 v1 = __half22float2(*(__half2*)&vcB.y);
                zB = zB * co + es;
                aB.x = aB.x * co + es * v0.x;
                aB.y = aB.y * co + es * v0.y;
                aB.z = aB.z * co + es * v1.x;
                aB.w = aB.w * co + es * v1.y;
            }
        }
    }
    float4 outv = make_float4(0.f, 0.f, 0.f, 0.f);
    if (e0 < e1) {
        float m = fmaxf(mA, mB);
        float cA = __expf(mA - m);
        float cB = __expf(mB - m);
        float z = zA * cA + zB * cB;
        float inv = 1.0f / (z + 1e-16f);
        outv.x = (aA.x * cA + aB.x * cB) * inv;
        outv.y = (aA.y * cA + aB.y * cB) * inv;
        outv.z = (aA.z * cA + aB.z * cB) * inv;
        outv.w = (aA.w * cA + aB.w * cB) * inv;
    }
    __half2 o0 = __floats2half2_rn(gelu_f(outv.x), gelu_f(outv.y));
    __half2 o1 = __floats2half2_rn(gelu_f(outv.z), gelu_f(outv.w));
    uint2 ov;
    ov.x = *(unsigned int*)&o0;
    ov.y = *(unsigned int*)&o1;
    *(uint2*)&g_aggh[gw * 128 + lane * 4] = ov;
}

// ---------------- Wout HMMA GEMM + skip + LayerNorm + cp.async ---------------
__global__ __launch_bounds__(256)
void k_wout_mma(const float* __restrict__ bout, const float* __restrict__ skip, int l,
                const float* __restrict__ ln_g, const float* __restrict__ ln_b) {
    __shared__ __half sA[2][128][40];
    __shared__ __half sB[2][32][136];
    __shared__ float s_rs[128], s_rq[128];
    int tid = threadIdx.x;
    int wid = tid >> 5, lane = tid & 31;
    int warp_m = (wid >> 2) * 64;
    int warp_n = (wid & 3) * 32;
    int row0 = blockIdx.x * 128;
    float acc[4][4][4];
    #pragma unroll
    for (int mi = 0; mi < 4; mi++)
        #pragma unroll
        for (int ni = 0; ni < 4; ni++)
            #pragma unroll
            for (int j = 0; j < 4; j++) acc[mi][ni][j] = 0.0f;

    int arow = tid >> 1, acol = (tid & 1) * 16;
    int brow = tid >> 3, bcol = (tid & 7) * 16;
    int gr = row0 + arow; if (gr >= NN) gr = NN - 1;
    const __half* agp = &g_aggh[gr * 128 + acol];
    const __half* bgp = &g_W2[brow * 128 + bcol];

#define LOAD_STAGE_W(st, kkv) do { \
    unsigned int dA = smem_u32(&sA[st][arow][acol]); \
    const __half* srcA = agp + (kkv) * 32; \
    CP_ASYNC16(dA, srcA); CP_ASYNC16(dA + 16, srcA + 8); \
    unsigned int dB = smem_u32(&sB[st][brow][bcol]); \
    const __half* srcB = bgp + (kkv) * 32 * 128; \
    CP_ASYNC16(dB, srcB); CP_ASYNC16(dB + 16, srcB + 8); \
    CP_COMMIT(); } while (0)

    LOAD_STAGE_W(0, 0);
    LOAD_STAGE_W(1, 1);

    #pragma unroll
    for (int kk4 = 0; kk4 < 4; kk4++) {
        int st = kk4 & 1;
        if (kk4 == 3) { CP_WAIT(0); } else { CP_WAIT(1); }
        __syncthreads();
        #pragma unroll
        for (int k16 = 0; k16 < 32; k16 += 16) {
            unsigned int af[4][4];
            #pragma unroll
            for (int mi = 0; mi < 4; mi++) {
                unsigned int ad = smem_u32(&sA[st][warp_m + mi * 16 + (lane & 15)][k16 + (lane >> 4) * 8]);
                LDSM_X4(af[mi][0], af[mi][1], af[mi][2], af[mi][3], ad);
            }
            unsigned int bf[4][2];
            #pragma unroll
            for (int nb = 0; nb < 2; nb++) {
                unsigned int bd = smem_u32(&sB[st][k16 + (lane & 15)][warp_n + nb * 16 + (lane >> 4) * 8]);
                unsigned int b0, b1_, b2, b3;
                LDSM_X4T(b0, b1_, b2, b3, bd);
                bf[nb * 2][0] = b0;     bf[nb * 2][1] = b1_;
                bf[nb * 2 + 1][0] = b2; bf[nb * 2 + 1][1] = b3;
            }
            #pragma unroll
            for (int mi = 0; mi < 4; mi++)
                #pragma unroll
                for (int ni = 0; ni < 4; ni++)
                    MMA16816(acc[mi][ni], af[mi], bf[ni]);
        }
        __syncthreads();
        if (kk4 + 2 < 4) LOAD_STAGE_W(st, kk4 + 2);
    }
#undef LOAD_STAGE_W

    if (tid < 128) { s_rs[tid] = 0.0f; s_rq[tid] = 0.0f; }
    __syncthreads();

    float alpha = 1.0f / (1.0f + expf(-skip[l]));
    float oma = 1.0f - alpha;
    int qrow = lane >> 2;
    int qcol = (lane & 3) * 2;
    float bb[4][2], gv[4][2], bv[4][2];
    #pragma unroll
    for (int ni = 0; ni < 4; ni++) {
        int col = warp_n + ni * 8 + qcol;
        bb[ni][0] = bout[col];     bb[ni][1] = bout[col + 1];
        gv[ni][0] = ln_g[col];     gv[ni][1] = ln_g[col + 1];
        bv[ni][0] = ln_b[col];     bv[ni][1] = ln_b[col + 1];
    }

    #pragma unroll
    for (int mi = 0; mi < 4; mi++) {
        int rl1 = warp_m + mi * 16 + qrow;
        int rl2 = rl1 + 8;
        int r1 = row0 + rl1, r2 = row0 + rl2;
        int cr1 = (r1 < NN) ? r1 : (NN - 1);
        int cr2 = (r2 < NN) ? r2 : (NN - 1);
        float s1 = 0.f, q1s = 0.f, s2 = 0.f, q2s = 0.f;
        #pragma unroll
        for (int ni = 0; ni < 4; ni++) {
            int col = warp_n + ni * 8 + qcol;
            float2 h1 = *(const float2*)&g_h[cr1 * 128 + col];
            float2 h2 = *(const float2*)&g_h[cr2 * 128 + col];
            float t00 = alpha * (acc[mi][ni][0] + bb[ni][0]) + oma * h1.x;
            float t01 = alpha * (acc[mi][ni][1] + bb[ni][1]) + oma * h1.y;
            float t10 = alpha * (acc[mi][ni][2] + bb[ni][0]) + oma * h2.x;
            float t11 = alpha * (acc[mi][ni][3] + bb[ni][1]) + oma * h2.y;
            acc[mi][ni][0] = t00; acc[mi][ni][1] = t01;
            acc[mi][ni][2] = t10; acc[mi][ni][3] = t11;
            s1 += t00 + t01; q1s += t00 * t00 + t01 * t01;
            s2 += t10 + t11; q2s += t10 * t10 + t11 * t11;
        }
        s1 += __shfl_xor_sync(0xffffffffu, s1, 1);
        s1 += __shfl_xor_sync(0xffffffffu, s1, 2);
        q1s += __shfl_xor_sync(0xffffffffu, q1s, 1);
        q1s += __shfl_xor_sync(0xffffffffu, q1s, 2);
        s2 += __shfl_xor_sync(0xffffffffu, s2, 1);
        s2 += __shfl_xor_sync(0xffffffffu, s2, 2);
        q2s += __shfl_xor_sync(0xffffffffu, q2s, 1);
        q2s += __shfl_xor_sync(0xffffffffu, q2s, 2);
        if ((lane & 3) == 0) {
            atomicAdd(&s_rs[rl1], s1); atomicAdd(&s_rq[rl1], q1s);
            atomicAdd(&s_rs[rl2], s2); atomicAdd(&s_rq[rl2], q2s);
        }
    }
    __syncthreads();

    #pragma unroll
    for (int mi = 0; mi < 4; mi++) {
        int rl1 = warp_m + mi * 16 + qrow;
        int rl2 = rl1 + 8;
        int r1 = row0 + rl1, r2 = row0 + rl2;
        float mu1 = s_rs[rl1] * (1.0f / 128.0f);
        float var1 = s_rq[rl1] * (1.0f / 128.0f) - mu1 * mu1;
        float rstd1 = rsqrtf(var1 + 1e-5f);
        float mu2 = s_rs[rl2] * (1.0f / 128.0f);
        float var2 = s_rq[rl2] * (1.0f / 128.0f) - mu2 * mu2;
        float rstd2 = rsqrtf(var2 + 1e-5f);
        #pragma unroll
        for (int ni = 0; ni < 4; ni++) {
            int col = warp_n + ni * 8 + qcol;
            float o00 = (acc[mi][ni][0] - mu1) * rstd1 * gv[ni][0] + bv[ni][0];
            float o01 = (acc[mi][ni][1] - mu1) * rstd1 * gv[ni][1] + bv[ni][1];
            float o10 = (acc[mi][ni][2] - mu2) * rstd2 * gv[ni][0] + bv[ni][0];
            float o11 = (acc[mi][ni][3] - mu2) * rstd2 * gv[ni][1] + bv[ni][1];
            if (r1 < NN) {
                *(float2*)&g_h[r1 * 128 + col] = make_float2(o00, o01);
                *(__half2*)&g_hh[r1 * 128 + col] = __floats2half2_rn(o00, o01);
            }
            if (r2 < NN) {
                *(float2*)&g_h[r2 * 128 + col] = make_float2(o10, o11);
                *(__half2*)&g_hh[r2 * 128 + col] = __floats2half2_rn(o10, o11);
            }
        }
    }
}

// ---------------- masked mean pool (batch sorted) ----------------------------
__global__ void k_pool(const float* __restrict__ x, const int* __restrict__ batch) {
    int c = threadIdx.x;  // 128
    int n0 = blockIdx.x * 512;
    int n1 = min(n0 + 512, NN);
    if (n0 >= NN) return;
    int curb = batch[n0];
    float a1 = 0.0f, a0 = 0.0f, c1 = 0.0f, c0 = 0.0f;
    for (int n = n0; n < n1; n++) {
        int b = batch[n];
        if (b != curb) {
            atomicAdd(&g_pool[curb * 128 + c], a1);
            atomicAdd(&g_pool[BB * 128 + curb * 128 + c], a0);
            if (c == 0) { atomicAdd(&g_cnt[curb], c1); atomicAdd(&g_cnt[BB + curb], c0); }
            a1 = a0 = c1 = c0 = 0.0f;
            curb = b;
        }
        float w = (x[n * 5 + 1] > 0.0f) ? 1.0f : 0.0f;
        float hv = g_h[n * 128 + c];
        a1 += w * hv;
        a0 += (1.0f - w) * hv;
        if (c == 0) { c1 += w; c0 += 1.0f - w; }
    }
    atomicAdd(&g_pool[curb * 128 + c], a1);
    atomicAdd(&g_pool[BB * 128 + curb * 128 + c], a0);
    if (c == 0) { atomicAdd(&g_cnt[curb], c1); atomicAdd(&g_cnt[BB + curb], c0); }
}

// ---------------- task fusion + head -----------------------------------------
__global__ void k_tf(const float* __restrict__ task, const float* __restrict__ Wtf,
                     const float* __restrict__ btf) {
    int b = blockIdx.x;
    int j = threadIdx.x;  // 256
    __shared__ float sin_[640];
    if (j < 128) {
        float c1 = g_cnt[b];
        sin_[j] = (c1 > 0.0f) ? g_pool[b * 128 + j] / c1 : 0.0f;
    } else {
        float c0 = g_cnt[BB + b];
        sin_[j] = (c0 > 0.0f) ? g_pool[BB * 128 + b * 128 + (j - 128)] / c0 : 0.0f;
    }
    for (int t = j; t < TASK; t += 256) sin_[256 + t] = task[b * TASK + t];
    __syncthreads();
    float acc = btf[j];
    for (int k = 0; k < 640; k++) acc += sin_[k] * Wtf[k * 256 + j];
    g_ge[b * 256 + j] = fmaxf(acc, 0.0f);
}

__global__ void k_head(const float* __restrict__ Wc1, const float* __restrict__ bc1,
                       const float* __restrict__ Wc2, const float* __restrict__ bc2,
                       float* __restrict__ out) {
    int b = blockIdx.x;
    int j = threadIdx.x;  // 64
    __shared__ float sge[256];
    __shared__ float red[64];
    for (int t = j; t < 256; t += 64) sge[t] = g_ge[b * 256 + t];
    __syncthreads();
    float acc = bc1[j];
    for (int k = 0; k < 256; k++) acc += sge[k] * Wc1[k * 64 + j];
    float hc = fmaxf(acc, 0.0f);
    red[j] = hc * Wc2[j];
    __syncthreads();
    for (int s = 32; s > 0; s >>= 1) {
        if (j < s) red[j] += red[j + s];
        __syncthreads();
    }
    if (j == 0) out[b] = red[0] + bc2[0];
}

// ---------------- host orchestration -----------------------------------------
extern "C" void kernel_launch(void* const* d_in, const int* in_sizes, int n_in,
                              void* d_out, int out_size) {
    const float* x      = (const float*)d_in[0];
    const int*   ast    = (const int*)  d_in[1];
    const int*   batch  = (const int*)  d_in[2];
    const int*   ei0    = (const int*)  d_in[3];
    const int*   ei1    = (const int*)  d_in[4];
    const int*   ei2    = (const int*)  d_in[5];
    const float* task   = (const float*)d_in[6];
    const float* emb    = (const float*)d_in[7];
    const float* Win    = (const float*)d_in[8];
    const float* bin    = (const float*)d_in[9];
    const float* Wkqv   = (const float*)d_in[10];
    const float* bkqv   = (const float*)d_in[11];
    const float* Wk_rel = (const float*)d_in[12];
    const float* Wv_rel = (const float*)d_in[13];
    const float* p_rel  = (const float*)d_in[14];
    const float* Wout   = (const float*)d_in[15];
    const float* bout   = (const float*)d_in[16];
    const float* skip   = (const float*)d_in[17];
    const float* ln_g   = (const float*)d_in[18];
    const float* ln_b   = (const float*)d_in[19];
    const float* Wtf    = (const float*)d_in[20];
    const float* btf    = (const float*)d_in[21];
    const float* Wc1    = (const float*)d_in[22];
    const float* bc1    = (const float*)d_in[23];
    const float* Wc2    = (const float*)d_in[24];
    const float* bc2    = (const float*)d_in[25];

    float *ppool, *pcnt;
    int *pdeg;
    cudaGetSymbolAddress((void**)&ppool, g_pool);
    cudaGetSymbolAddress((void**)&pcnt,  g_cnt);
    cudaGetSymbolAddress((void**)&pdeg,  g_deg);

    const int GEMM_GX = (NN + 127) / 128;
    const int GEMM_SMEM = 3 * 128 * 136 * (int)sizeof(__half);   // ~102 KB
    static int smem_set = 0;
    if (!smem_set) {
        cudaFuncSetAttribute(k_gemm_big, cudaFuncAttributeMaxDynamicSharedMemorySize,
                             GEMM_SMEM);
        smem_set = 1;
    }

    // CSR build interleaved with dense work
    k_filli<<<(NN + 255) / 256, 256>>>(pdeg, 0, NN);
    k_embed<<<NN / 32, 128>>>(x, ast, emb, Win, bin);
    k_hist<<<(ETOT + 255) / 256, 256>>>(ei0, ei1, ei2);
    k_combine<<<896, 128>>>(Wkqv, bkqv, Wk_rel, Wv_rel, 0);
    k_scan<<<1, 1024>>>();
    k_gemm_big<<<GEMM_GX, 256, GEMM_SMEM>>>();
    k_scatter<<<(ETOT + 255) / 256, 256>>>(ei0, ei1, ei2);
    k_wcvt<<<64, 256>>>(Wout, 0);
    k_edge<<<(NN + 7) / 8, 256>>>(p_rel);
    k_wout_mma<<<GEMM_GX, 256>>>(bout, skip, 0, ln_g, ln_b);

    // layer 1
    k_combine<<<896, 128>>>(Wkqv, bkqv, Wk_rel, Wv_rel, 1);
    k_gemm_big<<<GEMM_GX, 256, GEMM_SMEM>>>();
    k_wcvt<<<64, 256>>>(Wout, 1);
    k_edge<<<(NN + 7) / 8, 256>>>(p_rel + NREL * NHEAD);
    k_wout_mma<<<GEMM_GX, 256>>>(bout + HID, skip, 1, ln_g + HID, ln_b + HID);

    k_fill<<<(2 * BB * HID + 255) / 256, 256>>>(ppool, 0.0f, 2 * BB * HID);
    k_fill<<<1, 256>>>(pcnt, 0.0f, 2 * BB);
    k_pool<<<(NN + 511) / 512, 128>>>(x, batch);
    k_tf<<<BB, 256>>>(task, Wtf, btf);
    k_head<<<BB, 64>>>(Wc1, bc1, Wc2, bc2, (float*)d_out);
}

// round 16
// speedup vs baseline: 1.0499x; 1.0499x over previous
#include <cuda_runtime.h>
#include <cuda_fp16.h>
#include <math.h>
#include <stdint.h>

#define NN   200000
#define EE   300000
#define ETOT (3 * EE)
#define BB   64
#define HID  128
#define NHEAD 4
#define NREL 3
#define TED  64
#define TASK 384
#define INV_SQRT_D 0.17677669529663687f

// ---------------- scratch ----------------------------------------------------
__device__ float  g_h[NN * HID];           // fp32 node features
__device__ __half g_hh[NN * HID];          // fp16 shadow of g_h (GEMM A operand)
__device__ __half g_qh[NN * HID];          // queries fp16
__device__ __half g_kt[NREL][NN * HID];    // per-relation transformed keys
__device__ __half g_vt[NREL][NN * HID];    // per-relation transformed values
__device__ __half g_W1[128 * 896];         // fused weight [k=128][n=896]
__device__ float  g_b1[896];               // fused bias
__device__ __half g_W2[128 * 128];         // Wout fp16 [k][n]
__device__ __half g_aggh[NN * HID];        // gelu(agg) fp16
__device__ int    g_deg[NN];
__device__ int    g_off[NN + 1];
__device__ int    g_cur[NN];
__device__ int    g_edge[ETOT];            // src | (rel<<18), CSR order
__device__ float  g_pool[2 * BB * HID];
__device__ float  g_cnt[2 * BB];
__device__ float  g_ge[BB * 256];

// ---------------- helpers ----------------------------------------------------
__device__ __forceinline__ float gelu_f(float v) {
    return 0.5f * v * (1.0f + erff(v * 0.70710678118654752f));
}
#define PACKW(d_, lo_, hi_) asm("mov.b64 %0, {%1, %2};" : "=l"(d_) : "f"(lo_), "f"(hi_))
#define UNPK2(lo, hi, s) asm("mov.b64 {%0, %1}, %2;" : "=f"(lo), "=f"(hi) : "l"(s))
#define FFMA2(c_, a_, b_) \
    asm("fma.rn.f32x2 %0, %1, %2, %3;" : "=l"(c_) : "l"(a_), "l"(b_), "l"(c_))

__device__ __forceinline__ unsigned int smem_u32(const void* p) {
    return (unsigned int)__cvta_generic_to_shared(p);
}
#define CP_ASYNC16(dst, src) \
    asm volatile("cp.async.cg.shared.global [%0], [%1], 16;" :: "r"(dst), "l"(src))
#define CP_COMMIT() asm volatile("cp.async.commit_group;")
#define CP_WAIT(n)  asm volatile("cp.async.wait_group %0;" :: "n"(n))

#define LDSM_X4(r0,r1,r2,r3,addr) \
    asm volatile("ldmatrix.sync.aligned.m8n8.x4.shared.b16 {%0,%1,%2,%3}, [%4];" \
        : "=r"(r0),"=r"(r1),"=r"(r2),"=r"(r3) : "r"(addr))
#define LDSM_X4T(r0,r1,r2,r3,addr) \
    asm volatile("ldmatrix.sync.aligned.m8n8.x4.trans.shared.b16 {%0,%1,%2,%3}, [%4];" \
        : "=r"(r0),"=r"(r1),"=r"(r2),"=r"(r3) : "r"(addr))
#define MMA16816(d, a, b) \
    asm volatile("mma.sync.aligned.m16n8k16.row.col.f32.f16.f16.f32 " \
        "{%0,%1,%2,%3}, {%4,%5,%6,%7}, {%8,%9}, {%0,%1,%2,%3};" \
        : "+f"((d)[0]), "+f"((d)[1]), "+f"((d)[2]), "+f"((d)[3]) \
        : "r"((a)[0]), "r"((a)[1]), "r"((a)[2]), "r"((a)[3]), \
          "r"((b)[0]), "r"((b)[1]))

__global__ void k_fill(float* p, float v, int n) {
    int i = blockIdx.x * blockDim.x + threadIdx.x;
    if (i < n) p[i] = v;
}
__global__ void k_filli(int* p, int v, int n) {
    int i = blockIdx.x * blockDim.x + threadIdx.x;
    if (i < n) p[i] = v;
}

// ---------------- CSR build ---------------------------------------------------
__global__ void k_hist(const int* __restrict__ e0, const int* __restrict__ e1,
                       const int* __restrict__ e2) {
    int g = blockIdx.x * blockDim.x + threadIdx.x;
    if (g >= ETOT) return;
    int r = g / EE, e = g - r * EE;
    const int* ei = (r == 0) ? e0 : ((r == 1) ? e1 : e2);
    atomicAdd(&g_deg[ei[EE + e]], 1);
}

__global__ void k_scan() {   // single block, 1024 threads
    __shared__ int part[1024];
    int tid = threadIdx.x;
    const int CH = (NN + 1023) / 1024;
    int b0 = tid * CH, b1 = min(b0 + CH, NN);
    int s = 0;
    for (int i = b0; i < b1; i++) s += g_deg[i];
    part[tid] = s;
    __syncthreads();
    for (int off = 1; off < 1024; off <<= 1) {
        int v = (tid >= off) ? part[tid - off] : 0;
        __syncthreads();
        part[tid] += v;
        __syncthreads();
    }
    int run = (tid > 0) ? part[tid - 1] : 0;
    for (int i = b0; i < b1; i++) {
        int d = g_deg[i];
        g_off[i] = run;
        g_cur[i] = run;
        run += d;
    }
    if (tid == 1023) g_off[NN] = run;
}

__global__ void k_scatter(const int* __restrict__ e0, const int* __restrict__ e1,
                          const int* __restrict__ e2) {
    int g = blockIdx.x * blockDim.x + threadIdx.x;
    if (g >= ETOT) return;
    int r = g / EE, e = g - r * EE;
    const int* ei = (r == 0) ? e0 : ((r == 1) ? e1 : e2);
    int src = ei[e], dst = ei[EE + e];
    int pos = atomicAdd(&g_cur[dst], 1);
    g_edge[pos] = src | (r << 18);
}

// ---------------- input embed (FFMA2), writes fp32 + fp16 --------------------
__global__ void k_embed(const float* __restrict__ x, const int* __restrict__ ast,
                        const float* __restrict__ emb, const float* __restrict__ Win,
                        const float* __restrict__ bin) {
    __shared__ float sA[32][70];
    int tid = threadIdx.x;            // 128 = one output column per thread
    int c = tid;
    unsigned long long w2[34];
    #pragma unroll
    for (int t = 0; t < 34; t++) {
        float w0 = Win[(2 * t) * 128 + c];
        float w1 = Win[(2 * t + 1) * 128 + c];
        PACKW(w2[t], w0, w1);
    }
    float wl = Win[68 * 128 + c];
    float bv = bin[c];
    int n0 = blockIdx.x * 32;
    for (int idx = tid; idx < 32 * 69; idx += 128) {
        int i = idx / 69, k = idx - i * 69;
        int n = n0 + i;
        sA[i][k] = (k < TED) ? emb[ast[n] * TED + k] : x[n * 5 + (k - TED)];
    }
    __syncthreads();
    for (int i = 0; i < 32; i++) {
        const unsigned long long* ap = (const unsigned long long*)&sA[i][0];
        unsigned long long acc2 = 0ULL;
        #pragma unroll
        for (int t = 0; t < 34; t++) FFMA2(acc2, ap[t], w2[t]);
        float lo, hi;
        UNPK2(lo, hi, acc2);
        float val = bv + sA[i][68] * wl + lo + hi;
        g_h[(n0 + i) * HID + c] = val;
        g_hh[(n0 + i) * HID + c] = __float2half(val);
    }
}

// ---------------- combine weights + Wout cvt (folded) ------------------------
__global__ void k_combine(const float* __restrict__ Wkqv, const float* __restrict__ bkqv,
                          const float* __restrict__ Wk_rel, const float* __restrict__ Wv_rel,
                          const float* __restrict__ Wout, int l) {
    int n = blockIdx.x;      // 0..895
    int k = threadIdx.x;     // 0..127
    const float* Wl = Wkqv + l * 128 * 384;
    const float* bl = bkqv + l * 384;
    if (n < 128) {
        g_W1[k * 896 + n] = __float2half(Wl[k * 384 + 128 + n]);
        // folded Wout fp16 conversion: block n handles W2 row n
        g_W2[n * 128 + k] = __float2half(Wout[l * 128 * 128 + n * 128 + k]);
        if (k == 0) g_b1[n] = bl[128 + n];
        return;
    }
    int g = n - 128;
    int kv = g / 384;
    int rem = g - kv * 384;
    int r = rem >> 7;
    int c = rem & 127;
    int h = c >> 5, f = c & 31;
    const float* Wrel = ((kv == 0) ? Wk_rel : Wv_rel) + ((l * NREL + r) * NHEAD + h) * 1024;
    __shared__ float wcol[32];
    if (k < 32) wcol[k] = Wrel[k * 32 + f];
    __syncthreads();
    int off = (kv == 0) ? 0 : 256;
    const float* wrow = Wl + k * 384 + off + h * 32;
    float acc = 0.f;
    #pragma unroll
    for (int d = 0; d < 32; d++) acc += wrow[d] * wcol[d];
    g_W1[k * 896 + n] = __float2half(acc);
    if (k == 0) {
        float b = 0.f;
        #pragma unroll
        for (int d = 0; d < 32; d++) b += bl[off + h * 32 + d] * wcol[d];
        g_b1[n] = b;
    }
}

// ---------------- fused q/kt/vt GEMM: h[N,128] @ W1[128,896], HMMA + cp.async
__global__ __launch_bounds__(256)
void k_gemm_big() {
    __shared__ __half sA[2][128][40];
    __shared__ __half sB[2][32][136];
    int tid = threadIdx.x;
    int wid = tid >> 5, lane = tid & 31;
    int warp_m = (wid >> 2) * 64;
    int warp_n = (wid & 3) * 32;
    int row0 = blockIdx.x * 128;
    int y = blockIdx.y;               // 0=q, 1..3=kt, 4..6=vt
    int ncol0 = y * 128;
    float acc[4][4][4];
    #pragma unroll
    for (int mi = 0; mi < 4; mi++)
        #pragma unroll
        for (int ni = 0; ni < 4; ni++)
            #pragma unroll
            for (int j = 0; j < 4; j++) acc[mi][ni][j] = 0.0f;

    int arow = tid >> 1, acol = (tid & 1) * 16;
    int brow = tid >> 3, bcol = (tid & 7) * 16;
    int gr = row0 + arow; if (gr >= NN) gr = NN - 1;
    const __half* agp = &g_hh[gr * 128 + acol];
    const __half* bgp = &g_W1[brow * 896 + ncol0 + bcol];

#define LOAD_STAGE_BIG(st, kkv) do { \
    unsigned int dA = smem_u32(&sA[st][arow][acol]); \
    const __half* srcA = agp + (kkv) * 32; \
    CP_ASYNC16(dA, srcA); CP_ASYNC16(dA + 16, srcA + 8); \
    unsigned int dB = smem_u32(&sB[st][brow][bcol]); \
    const __half* srcB = bgp + (kkv) * 32 * 896; \
    CP_ASYNC16(dB, srcB); CP_ASYNC16(dB + 16, srcB + 8); \
    CP_COMMIT(); } while (0)

    LOAD_STAGE_BIG(0, 0);
    LOAD_STAGE_BIG(1, 1);

    #pragma unroll
    for (int kk4 = 0; kk4 < 4; kk4++) {
        int st = kk4 & 1;
        if (kk4 == 3) { CP_WAIT(0); } else { CP_WAIT(1); }
        __syncthreads();
        #pragma unroll
        for (int k16 = 0; k16 < 32; k16 += 16) {
            unsigned int af[4][4];
            #pragma unroll
            for (int mi = 0; mi < 4; mi++) {
                unsigned int ad = smem_u32(&sA[st][warp_m + mi * 16 + (lane & 15)][k16 + (lane >> 4) * 8]);
                LDSM_X4(af[mi][0], af[mi][1], af[mi][2], af[mi][3], ad);
            }
            unsigned int bf[4][2];
            #pragma unroll
            for (int nb = 0; nb < 2; nb++) {
                unsigned int bd = smem_u32(&sB[st][k16 + (lane & 15)][warp_n + nb * 16 + (lane >> 4) * 8]);
                unsigned int b0, b1_, b2, b3;
                LDSM_X4T(b0, b1_, b2, b3, bd);
                bf[nb * 2][0] = b0;     bf[nb * 2][1] = b1_;
                bf[nb * 2 + 1][0] = b2; bf[nb * 2 + 1][1] = b3;
            }
            #pragma unroll
            for (int mi = 0; mi < 4; mi++)
                #pragma unroll
                for (int ni = 0; ni < 4; ni++)
                    MMA16816(acc[mi][ni], af[mi], bf[ni]);
        }
        __syncthreads();
        if (kk4 + 2 < 4) LOAD_STAGE_BIG(st, kk4 + 2);
    }
#undef LOAD_STAGE_BIG

    int qrow = lane >> 2;
    int qcol = (lane & 3) * 2;
    float bb[4][2];
    #pragma unroll
    for (int ni = 0; ni < 4; ni++) {
        int col = warp_n + ni * 8 + qcol;
        bb[ni][0] = g_b1[ncol0 + col];
        bb[ni][1] = g_b1[ncol0 + col + 1];
    }
    __half* dsth = (y == 0) ? g_qh : ((y <= 3) ? g_kt[y - 1] : g_vt[y - 4]);
    #pragma unroll
    for (int mi = 0; mi < 4; mi++) {
        #pragma unroll
        for (int ni = 0; ni < 4; ni++) {
            int col = warp_n + ni * 8 + qcol;
            int r1 = row0 + warp_m + mi * 16 + qrow;
            int r2 = r1 + 8;
            float v00 = acc[mi][ni][0] + bb[ni][0], v01 = acc[mi][ni][1] + bb[ni][1];
            float v10 = acc[mi][ni][2] + bb[ni][0], v11 = acc[mi][ni][3] + bb[ni][1];
            if (r1 < NN) *(__half2*)&dsth[r1 * 128 + col] = __floats2half2_rn(v00, v01);
            if (r2 < NN) *(__half2*)&dsth[r2 * 128 + col] = __floats2half2_rn(v10, v11);
        }
    }
}

// ---------------- fused edge attention: 2-state online softmax ---------------
__global__ __launch_bounds__(256)
void k_edge(const float* __restrict__ prel) {
    int gw = (blockIdx.x * blockDim.x + threadIdx.x) >> 5;
    if (gw >= NN) return;
    int lane = threadIdx.x & 31;
    int h = lane >> 3;
    float p0 = prel[h] * INV_SQRT_D;
    float p1 = prel[4 + h] * INV_SQRT_D;
    float p2 = prel[8 + h] * INV_SQRT_D;
    uint2 qraw = *(const uint2*)&g_qh[gw * 128 + lane * 4];
    float2 q0 = __half22float2(*(__half2*)&qraw.x);
    float2 q1 = __half22float2(*(__half2*)&qraw.y);
    int e0 = g_off[gw], e1 = g_off[gw + 1];
    float mA = -INFINITY, zA = 0.0f;
    float mB = -INFINITY, zB = 0.0f;
    float4 aA = make_float4(0.f, 0.f, 0.f, 0.f);
    float4 aB = make_float4(0.f, 0.f, 0.f, 0.f);
    if (e0 < e1) {
        int pkA = g_edge[e0], pkB = 0;
        uint2 kA, vA;
        uint2 kB = make_uint2(0u, 0u), vB = make_uint2(0u, 0u);
        {
            int s = pkA & 0x3FFFF, r = pkA >> 18;
            kA = *(const uint2*)&g_kt[r][s * 128 + lane * 4];
            vA = *(const uint2*)&g_vt[r][s * 128 + lane * 4];
        }
        if (e0 + 1 < e1) {
            pkB = g_edge[e0 + 1];
            int s = pkB & 0x3FFFF, r = pkB >> 18;
            kB = *(const uint2*)&g_kt[r][s * 128 + lane * 4];
            vB = *(const uint2*)&g_vt[r][s * 128 + lane * 4];
        }
        for (int i = e0; i < e1; i += 2) {
            int rcA = pkA >> 18; uint2 kcA = kA, vcA = vA;
            bool hasB = (i + 1 < e1);
            int rcB = pkB >> 18; uint2 kcB = kB, vcB = vB;
            if (i + 2 < e1) {
                pkA = g_edge[i + 2];
                int s = pkA & 0x3FFFF, r = pkA >> 18;
                kA = *(const uint2*)&g_kt[r][s * 128 + lane * 4];
                vA = *(const uint2*)&g_vt[r][s * 128 + lane * 4];
            }
            if (i + 3 < e1) {
                pkB = g_edge[i + 3];
                int s = pkB & 0x3FFFF, r = pkB >> 18;
                kB = *(const uint2*)&g_kt[r][s * 128 + lane * 4];
                vB = *(const uint2*)&g_vt[r][s * 128 + lane * 4];
            }
            float2 ka0 = __half22float2(*(__half2*)&kcA.x);
            float2 ka1 = __half22float2(*(__half2*)&kcA.y);
            float sA_ = q0.x * ka0.x + q0.y * ka0.y + q1.x * ka1.x + q1.y * ka1.y;
            float2 kb0 = __half22float2(*(__half2*)&kcB.x);
            float2 kb1 = __half22float2(*(__half2*)&kcB.y);
            float sB_ = q0.x * kb0.x + q0.y * kb0.y + q1.x * kb1.x + q1.y * kb1.y;
            sA_ += __shfl_xor_sync(0xffffffffu, sA_, 1);
            sB_ += __shfl_xor_sync(0xffffffffu, sB_, 1);
            sA_ += __shfl_xor_sync(0xffffffffu, sA_, 2);
            sB_ += __shfl_xor_sync(0xffffffffu, sB_, 2);
            sA_ += __shfl_xor_sync(0xffffffffu, sA_, 4);
            sB_ += __shfl_xor_sync(0xffffffffu, sB_, 4);
            sA_ *= (rcA == 0) ? p0 : ((rcA == 1) ? p1 : p2);
            sB_ *= (rcB == 0) ? p0 : ((rcB == 1) ? p1 : p2);
            {
                float mn = fmaxf(mA, sA_);
                float es = __expf(sA_ - mn);
                float co = __expf(mA - mn);
                mA = mn;
                float2 v0 = __half22float2(*(__half2*)&vcA.x);
                float2 v1 = __half22float2(*(__half2*)&vcA.y);
                zA = zA * co + es;
                aA.x = aA.x * co + es * v0.x;
                aA.y = aA.y * co + es * v0.y;
                aA.z = aA.z * co + es * v1.x;
                aA.w = aA.w * co + es * v1.y;
            }
            if (hasB) {
                float mn = fmaxf(mB, sB_);
                float es = __expf(sB_ - mn);
                float co = __expf(mB - mn);
                mB = mn;
                float2 v0 = __half22float2(*(__half2*)&vcB.x);
                float2 v1 = __half22float2(*(__half2*)&vcB.y);
                zB = zB * co + es;
                aB.x = aB.x * co + es * v0.x;
                aB.y = aB.y * co + es * v0.y;
                aB.z = aB.z * co + es * v1.x;
                aB.w = aB.w * co + es * v1.y;
            }
        }
    }
    float4 outv = make_float4(0.f, 0.f, 0.f, 0.f);
    if (e0 < e1) {
        float m = fmaxf(mA, mB);
        float cA = __expf(mA - m);
        float cB = __expf(mB - m);
        float z = zA * cA + zB * cB;
        float inv = 1.0f / (z + 1e-16f);
        outv.x = (aA.x * cA + aB.x * cB) * inv;
        outv.y = (aA.y * cA + aB.y * cB) * inv;
        outv.z = (aA.z * cA + aB.z * cB) * inv;
        outv.w = (aA.w * cA + aB.w * cB) * inv;
    }
    __half2 o0 = __floats2half2_rn(gelu_f(outv.x), gelu_f(outv.y));
    __half2 o1 = __floats2half2_rn(gelu_f(outv.z), gelu_f(outv.w));
    uint2 ov;
    ov.x = *(unsigned int*)&o0;
    ov.y = *(unsigned int*)&o1;
    *(uint2*)&g_aggh[gw * 128 + lane * 4] = ov;
}

// ---------------- Wout HMMA GEMM + skip + LayerNorm + cp.async ---------------
__global__ __launch_bounds__(256)
void k_wout_mma(const float* __restrict__ bout, const float* __restrict__ skip, int l,
                const float* __restrict__ ln_g, const float* __restrict__ ln_b) {
    __shared__ __half sA[2][128][40];
    __shared__ __half sB[2][32][136];
    __shared__ float s_rs[128], s_rq[128];
    int tid = threadIdx.x;
    int wid = tid >> 5, lane = tid & 31;
    int warp_m = (wid >> 2) * 64;
    int warp_n = (wid & 3) * 32;
    int row0 = blockIdx.x * 128;
    float acc[4][4][4];
    #pragma unroll
    for (int mi = 0; mi < 4; mi++)
        #pragma unroll
        for (int ni = 0; ni < 4; ni++)
            #pragma unroll
            for (int j = 0; j < 4; j++) acc[mi][ni][j] = 0.0f;

    int arow = tid >> 1, acol = (tid & 1) * 16;
    int brow = tid >> 3, bcol = (tid & 7) * 16;
    int gr = row0 + arow; if (gr >= NN) gr = NN - 1;
    const __half* agp = &g_aggh[gr * 128 + acol];
    const __half* bgp = &g_W2[brow * 128 + bcol];

#define LOAD_STAGE_W(st, kkv) do { \
    unsigned int dA = smem_u32(&sA[st][arow][acol]); \
    const __half* srcA = agp + (kkv) * 32; \
    CP_ASYNC16(dA, srcA); CP_ASYNC16(dA + 16, srcA + 8); \
    unsigned int dB = smem_u32(&sB[st][brow][bcol]); \
    const __half* srcB = bgp + (kkv) * 32 * 128; \
    CP_ASYNC16(dB, srcB); CP_ASYNC16(dB + 16, srcB + 8); \
    CP_COMMIT(); } while (0)

    LOAD_STAGE_W(0, 0);
    LOAD_STAGE_W(1, 1);

    #pragma unroll
    for (int kk4 = 0; kk4 < 4; kk4++) {
        int st = kk4 & 1;
        if (kk4 == 3) { CP_WAIT(0); } else { CP_WAIT(1); }
        __syncthreads();
        #pragma unroll
        for (int k16 = 0; k16 < 32; k16 += 16) {
            unsigned int af[4][4];
            #pragma unroll
            for (int mi = 0; mi < 4; mi++) {
                unsigned int ad = smem_u32(&sA[st][warp_m + mi * 16 + (lane & 15)][k16 + (lane >> 4) * 8]);
                LDSM_X4(af[mi][0], af[mi][1], af[mi][2], af[mi][3], ad);
            }
            unsigned int bf[4][2];
            #pragma unroll
            for (int nb = 0; nb < 2; nb++) {
                unsigned int bd = smem_u32(&sB[st][k16 + (lane & 15)][warp_n + nb * 16 + (lane >> 4) * 8]);
                unsigned int b0, b1_, b2, b3;
                LDSM_X4T(b0, b1_, b2, b3, bd);
                bf[nb * 2][0] = b0;     bf[nb * 2][1] = b1_;
                bf[nb * 2 + 1][0] = b2; bf[nb * 2 + 1][1] = b3;
            }
            #pragma unroll
            for (int mi = 0; mi < 4; mi++)
                #pragma unroll
                for (int ni = 0; ni < 4; ni++)
                    MMA16816(acc[mi][ni], af[mi], bf[ni]);
        }
        __syncthreads();
        if (kk4 + 2 < 4) LOAD_STAGE_W(st, kk4 + 2);
    }
#undef LOAD_STAGE_W

    if (tid < 128) { s_rs[tid] = 0.0f; s_rq[tid] = 0.0f; }
    __syncthreads();

    float alpha = 1.0f / (1.0f + expf(-skip[l]));
    float oma = 1.0f - alpha;
    int qrow = lane >> 2;
    int qcol = (lane & 3) * 2;
    float bb[4][2], gv[4][2], bv[4][2];
    #pragma unroll
    for (int ni = 0; ni < 4; ni++) {
        int col = warp_n + ni * 8 + qcol;
        bb[ni][0] = bout[col];     bb[ni][1] = bout[col + 1];
        gv[ni][0] = ln_g[col];     gv[ni][1] = ln_g[col + 1];
        bv[ni][0] = ln_b[col];     bv[ni][1] = ln_b[col + 1];
    }

    #pragma unroll
    for (int mi = 0; mi < 4; mi++) {
        int rl1 = warp_m + mi * 16 + qrow;
        int rl2 = rl1 + 8;
        int r1 = row0 + rl1, r2 = row0 + rl2;
        int cr1 = (r1 < NN) ? r1 : (NN - 1);
        int cr2 = (r2 < NN) ? r2 : (NN - 1);
        float s1 = 0.f, q1s = 0.f, s2 = 0.f, q2s = 0.f;
        #pragma unroll
        for (int ni = 0; ni < 4; ni++) {
            int col = warp_n + ni * 8 + qcol;
            float2 h1 = *(const float2*)&g_h[cr1 * 128 + col];
            float2 h2 = *(const float2*)&g_h[cr2 * 128 + col];
            float t00 = alpha * (acc[mi][ni][0] + bb[ni][0]) + oma * h1.x;
            float t01 = alpha * (acc[mi][ni][1] + bb[ni][1]) + oma * h1.y;
            float t10 = alpha * (acc[mi][ni][2] + bb[ni][0]) + oma * h2.x;
            float t11 = alpha * (acc[mi][ni][3] + bb[ni][1]) + oma * h2.y;
            acc[mi][ni][0] = t00; acc[mi][ni][1] = t01;
            acc[mi][ni][2] = t10; acc[mi][ni][3] = t11;
            s1 += t00 + t01; q1s += t00 * t00 + t01 * t01;
            s2 += t10 + t11; q2s += t10 * t10 + t11 * t11;
        }
        s1 += __shfl_xor_sync(0xffffffffu, s1, 1);
        s1 += __shfl_xor_sync(0xffffffffu, s1, 2);
        q1s += __shfl_xor_sync(0xffffffffu, q1s, 1);
        q1s += __shfl_xor_sync(0xffffffffu, q1s, 2);
        s2 += __shfl_xor_sync(0xffffffffu, s2, 1);
        s2 += __shfl_xor_sync(0xffffffffu, s2, 2);
        q2s += __shfl_xor_sync(0xffffffffu, q2s, 1);
        q2s += __shfl_xor_sync(0xffffffffu, q2s, 2);
        if ((lane & 3) == 0) {
            atomicAdd(&s_rs[rl1], s1); atomicAdd(&s_rq[rl1], q1s);
            atomicAdd(&s_rs[rl2], s2); atomicAdd(&s_rq[rl2], q2s);
        }
    }
    __syncthreads();

    #pragma unroll
    for (int mi = 0; mi < 4; mi++) {
        int rl1 = warp_m + mi * 16 + qrow;
        int rl2 = rl1 + 8;
        int r1 = row0 + rl1, r2 = row0 + rl2;
        float mu1 = s_rs[rl1] * (1.0f / 128.0f);
        float var1 = s_rq[rl1] * (1.0f / 128.0f) - mu1 * mu1;
        float rstd1 = rsqrtf(var1 + 1e-5f);
        float mu2 = s_rs[rl2] * (1.0f / 128.0f);
        float var2 = s_rq[rl2] * (1.0f / 128.0f) - mu2 * mu2;
        float rstd2 = rsqrtf(var2 + 1e-5f);
        #pragma unroll
        for (int ni = 0; ni < 4; ni++) {
            int col = warp_n + ni * 8 + qcol;
            float o00 = (acc[mi][ni][0] - mu1) * rstd1 * gv[ni][0] + bv[ni][0];
            float o01 = (acc[mi][ni][1] - mu1) * rstd1 * gv[ni][1] + bv[ni][1];
            float o10 = (acc[mi][ni][2] - mu2) * rstd2 * gv[ni][0] + bv[ni][0];
            float o11 = (acc[mi][ni][3] - mu2) * rstd2 * gv[ni][1] + bv[ni][1];
            if (r1 < NN) {
                *(float2*)&g_h[r1 * 128 + col] = make_float2(o00, o01);
                *(__half2*)&g_hh[r1 * 128 + col] = __floats2half2_rn(o00, o01);
            }
            if (r2 < NN) {
                *(float2*)&g_h[r2 * 128 + col] = make_float2(o10, o11);
                *(__half2*)&g_hh[r2 * 128 + col] = __floats2half2_rn(o10, o11);
            }
        }
    }
}

// ---------------- masked mean pool (batch sorted) ----------------------------
__global__ void k_pool(const float* __restrict__ x, const int* __restrict__ batch) {
    int c = threadIdx.x;  // 128
    int n0 = blockIdx.x * 512;
    int n1 = min(n0 + 512, NN);
    if (n0 >= NN) return;
    int curb = batch[n0];
    float a1 = 0.0f, a0 = 0.0f, c1 = 0.0f, c0 = 0.0f;
    for (int n = n0; n < n1; n++) {
        int b = batch[n];
        if (b != curb) {
            atomicAdd(&g_pool[curb * 128 + c], a1);
            atomicAdd(&g_pool[BB * 128 + curb * 128 + c], a0);
            if (c == 0) { atomicAdd(&g_cnt[curb], c1); atomicAdd(&g_cnt[BB + curb], c0); }
            a1 = a0 = c1 = c0 = 0.0f;
            curb = b;
        }
        float w = (x[n * 5 + 1] > 0.0f) ? 1.0f : 0.0f;
        float hv = g_h[n * 128 + c];
        a1 += w * hv;
        a0 += (1.0f - w) * hv;
        if (c == 0) { c1 += w; c0 += 1.0f - w; }
    }
    atomicAdd(&g_pool[curb * 128 + c], a1);
    atomicAdd(&g_pool[BB * 128 + curb * 128 + c], a0);
    if (c == 0) { atomicAdd(&g_cnt[curb], c1); atomicAdd(&g_cnt[BB + curb], c0); }
}

// ---------------- task fusion + head -----------------------------------------
__global__ void k_tf(const float* __restrict__ task, const float* __restrict__ Wtf,
                     const float* __restrict__ btf) {
    int b = blockIdx.x;
    int j = threadIdx.x;  // 256
    __shared__ float sin_[640];
    if (j < 128) {
        float c1 = g_cnt[b];
        sin_[j] = (c1 > 0.0f) ? g_pool[b * 128 + j] / c1 : 0.0f;
    } else {
        float c0 = g_cnt[BB + b];
        sin_[j] = (c0 > 0.0f) ? g_pool[BB * 128 + b * 128 + (j - 128)] / c0 : 0.0f;
    }
    for (int t = j; t < TASK; t += 256) sin_[256 + t] = task[b * TASK + t];
    __syncthreads();
    float acc = btf[j];
    for (int k = 0; k < 640; k++) acc += sin_[k] * Wtf[k * 256 + j];
    g_ge[b * 256 + j] = fmaxf(acc, 0.0f);
}

__global__ void k_head(const float* __restrict__ Wc1, const float* __restrict__ bc1,
                       const float* __restrict__ Wc2, const float* __restrict__ bc2,
                       float* __restrict__ out) {
    int b = blockIdx.x;
    int j = threadIdx.x;  // 64
    __shared__ float sge[256];
    __shared__ float red[64];
    for (int t = j; t < 256; t += 64) sge[t] = g_ge[b * 256 + t];
    __syncthreads();
    float acc = bc1[j];
    for (int k = 0; k < 256; k++) acc += sge[k] * Wc1[k * 64 + j];
    float hc = fmaxf(acc, 0.0f);
    red[j] = hc * Wc2[j];
    __syncthreads();
    for (int s = 32; s > 0; s >>= 1) {
        if (j < s) red[j] += red[j + s];
        __syncthreads();
    }
    if (j == 0) out[b] = red[0] + bc2[0];
}

// ---------------- host orchestration -----------------------------------------
extern "C" void kernel_launch(void* const* d_in, const int* in_sizes, int n_in,
                              void* d_out, int out_size) {
    const float* x      = (const float*)d_in[0];
    const int*   ast    = (const int*)  d_in[1];
    const int*   batch  = (const int*)  d_in[2];
    const int*   ei0    = (const int*)  d_in[3];
    const int*   ei1    = (const int*)  d_in[4];
    const int*   ei2    = (const int*)  d_in[5];
    const float* task   = (const float*)d_in[6];
    const float* emb    = (const float*)d_in[7];
    const float* Win    = (const float*)d_in[8];
    const float* bin    = (const float*)d_in[9];
    const float* Wkqv   = (const float*)d_in[10];
    const float* bkqv   = (const float*)d_in[11];
    const float* Wk_rel = (const float*)d_in[12];
    const float* Wv_rel = (const float*)d_in[13];
    const float* p_rel  = (const float*)d_in[14];
    const float* Wout   = (const float*)d_in[15];
    const float* bout   = (const float*)d_in[16];
    const float* skip   = (const float*)d_in[17];
    const float* ln_g   = (const float*)d_in[18];
    const float* ln_b   = (const float*)d_in[19];
    const float* Wtf    = (const float*)d_in[20];
    const float* btf    = (const float*)d_in[21];
    const float* Wc1    = (const float*)d_in[22];
    const float* bc1    = (const float*)d_in[23];
    const float* Wc2    = (const float*)d_in[24];
    const float* bc2    = (const float*)d_in[25];

    float *ppool, *pcnt;
    int *pdeg;
    cudaGetSymbolAddress((void**)&ppool, g_pool);
    cudaGetSymbolAddress((void**)&pcnt,  g_cnt);
    cudaGetSymbolAddress((void**)&pdeg,  g_deg);

    const int GEMM_GX = (NN + 127) / 128;

    // CSR build interleaved with dense work
    k_filli<<<(NN + 255) / 256, 256>>>(pdeg, 0, NN);
    k_embed<<<NN / 32, 128>>>(x, ast, emb, Win, bin);
    k_hist<<<(ETOT + 255) / 256, 256>>>(ei0, ei1, ei2);
    k_combine<<<896, 128>>>(Wkqv, bkqv, Wk_rel, Wv_rel, Wout, 0);
    k_scan<<<1, 1024>>>();
    k_gemm_big<<<dim3(GEMM_GX, 7), 256>>>();
    k_scatter<<<(ETOT + 255) / 256, 256>>>(ei0, ei1, ei2);
    k_edge<<<(NN + 7) / 8, 256>>>(p_rel);
    k_wout_mma<<<GEMM_GX, 256>>>(bout, skip, 0, ln_g, ln_b);

    // layer 1
    k_combine<<<896, 128>>>(Wkqv, bkqv, Wk_rel, Wv_rel, Wout, 1);
    k_gemm_big<<<dim3(GEMM_GX, 7), 256>>>();
    k_edge<<<(NN + 7) / 8, 256>>>(p_rel + NREL * NHEAD);
    k_wout_mma<<<GEMM_GX, 256>>>(bout + HID, skip, 1, ln_g + HID, ln_b + HID);

    k_fill<<<(2 * BB * HID + 255) / 256, 256>>>(ppool, 0.0f, 2 * BB * HID);
    k_fill<<<1, 256>>>(pcnt, 0.0f, 2 * BB);
    k_pool<<<(NN + 511) / 512, 128>>>(x, batch);
    k_tf<<<BB, 256>>>(task, Wtf, btf);
    k_head<<<BB, 64>>>(Wc1, bc1, Wc2, bc2, (float*)d_out);
}